// round 7
// baseline (speedup 1.0000x reference)
#include <cuda_runtime.h>
#include <cuda_bf16.h>
#include <cstdint>

// Problem constants (fixed by the reference)
#define HDIM 2048      // H
#define NEXP 8         // E
#define NTOK 2048      // T
#define FDIM 4096      // 2*INTER

// Scratch (no device allocation allowed)
__device__ float  g_v[NEXP * HDIM];
__device__ double g_acc;

// ---------------------------------------------------------------------------
// Kernel 0: zero scratch (must run every replay — graph replays kernel_launch)
// ---------------------------------------------------------------------------
__global__ void init_kernel() {
    int i = blockIdx.x * blockDim.x + threadIdx.x;
    if (i == 0) g_acc = 0.0;
    for (int j = i; j < NEXP * HDIM; j += gridDim.x * blockDim.x)
        g_v[j] = 0.0f;
}

// ---------------------------------------------------------------------------
// Kernel 1: v[e,h] = sum_t mask[e,t] * hidden[t,h]
// grid (H/512, 32), block 128. Each thread owns 4 consecutive h (float4),
// 8 expert accumulators each; each block covers a 64-token chunk.
// hidden read exactly once (16 MB).
// ---------------------------------------------------------------------------
__global__ void __launch_bounds__(128)
v_kernel(const float* __restrict__ hidden, const float* __restrict__ mask) {
    const int TC = NTOK / 32;              // 64 tokens per block (gridDim.y = 32)
    __shared__ float smask[NEXP][TC];

    const int t0 = blockIdx.y * TC;
    for (int i = threadIdx.x; i < NEXP * TC; i += blockDim.x) {
        int e = i / TC, t = i % TC;
        smask[e][t] = mask[e * NTOK + t0 + t];
    }
    __syncthreads();

    const int h4 = blockIdx.x * blockDim.x + threadIdx.x;   // float4 column index
    float acc[NEXP][4];
    #pragma unroll
    for (int e = 0; e < NEXP; e++)
        #pragma unroll
        for (int c = 0; c < 4; c++) acc[e][c] = 0.0f;

    const float4* hid4 = reinterpret_cast<const float4*>(hidden);
    #pragma unroll 4
    for (int tt = 0; tt < TC; ++tt) {
        float4 hv = hid4[(size_t)(t0 + tt) * (HDIM / 4) + h4];
        #pragma unroll
        for (int e = 0; e < NEXP; e++) {
            float m = smask[e][tt];
            acc[e][0] = fmaf(m, hv.x, acc[e][0]);
            acc[e][1] = fmaf(m, hv.y, acc[e][1]);
            acc[e][2] = fmaf(m, hv.z, acc[e][2]);
            acc[e][3] = fmaf(m, hv.w, acc[e][3]);
        }
    }

    const int h = h4 * 4;
    #pragma unroll
    for (int e = 0; e < NEXP; e++)
        #pragma unroll
        for (int c = 0; c < 4; c++)
            atomicAdd(&g_v[e * HDIM + h + c], acc[e][c]);
}

// ---------------------------------------------------------------------------
// Kernel 2 (the 256 MB pass): per row r=(e,h): w = sum_f W[r,f]; acc += w*v[r]
// One warp per row, 32 float4 LDGs per lane fully unrolled (high MLP).
// Block = 256 threads = 8 rows; grid = 16384/8 = 2048 blocks.
// ---------------------------------------------------------------------------
__global__ void __launch_bounds__(256)
dot_kernel(const float* __restrict__ W) {
    const int warp_in_blk = threadIdx.x >> 5;
    const int lane        = threadIdx.x & 31;
    const int row         = blockIdx.x * (blockDim.x >> 5) + warp_in_blk;  // 0..16383

    const float4* w4 = reinterpret_cast<const float4*>(W + (size_t)row * FDIM);

    float s = 0.0f;
    #pragma unroll
    for (int i = 0; i < FDIM / (32 * 4); ++i) {          // 32 independent LDG.128
        float4 v = w4[i * 32 + lane];
        s += (v.x + v.y) + (v.z + v.w);
    }
    #pragma unroll
    for (int off = 16; off; off >>= 1)
        s += __shfl_xor_sync(0xffffffffu, s, off);

    __shared__ double ssum[8];
    if (lane == 0)
        ssum[warp_in_blk] = (double)s * (double)g_v[row];
    __syncthreads();

    if (threadIdx.x == 0) {
        double tot = 0.0;
        #pragma unroll
        for (int i = 0; i < 8; i++) tot += ssum[i];
        atomicAdd(&g_acc, tot);
    }
}

// ---------------------------------------------------------------------------
// Kernel 3: emit scalar
// ---------------------------------------------------------------------------
__global__ void finalize_kernel(float* __restrict__ out, int out_size) {
    int i = blockIdx.x * blockDim.x + threadIdx.x;
    if (i < out_size) out[i] = (i == 0) ? (float)g_acc : 0.0f;
}

// ---------------------------------------------------------------------------
// Launch contract
//   d_in[0] = hidden_4d   [1,1,T,H]   float32  (T*H elements)
//   d_in[1] = gate_up_proj[1,E,H,F]   float32  (E*H*F elements)
//   d_in[2] = sparsity    [1,E,T,1]   float32  (E*T elements)
//   d_out   = scalar float32
// ---------------------------------------------------------------------------
extern "C" void kernel_launch(void* const* d_in, const int* in_sizes, int n_in,
                              void* d_out, int out_size) {
    const float* hidden = (const float*)d_in[0];
    const float* W      = (const float*)d_in[1];
    const float* mask   = (const float*)d_in[2];
    float* out          = (float*)d_out;

    init_kernel<<<64, 256>>>();

    dim3 vgrid(HDIM / 4 / 128, 32);           // (4, 32) blocks of 128 threads
    v_kernel<<<vgrid, 128>>>(hidden, mask);

    const int rows = NEXP * HDIM;             // 16384
    dot_kernel<<<rows / 8, 256>>>(W);

    finalize_kernel<<<(out_size + 255) / 256, 256>>>(out, out_size);
}

// round 8
// speedup vs baseline: 1.1119x; 1.1119x over previous
#include <cuda_runtime.h>
#include <cuda_bf16.h>
#include <cstdint>

// Problem constants (fixed by the reference)
#define HDIM 2048                       // H
#define NEXP 8                          // E
#define NTOK 2048                       // T
#define FDIM 4096                       // 2*INTER
#define ROWS (NEXP * HDIM)              // 16384 (e,h) rows of W

// Block layout: v-blocks first (wave-1 guaranteed), then W-row blocks.
#define NV_BLOCKS 64                    // 32 token-chunks x 2 column-groups
#define ROWS_PER_BLOCK 8                // 8 warps per block, 1 row per warp
#define NW_BLOCKS (ROWS / ROWS_PER_BLOCK)        // 2048
#define TOTAL_BLOCKS (NV_BLOCKS + NW_BLOCKS)     // 2112

// Scratch (__device__ globals; no allocation allowed).
// Invariant: g_v == 0 and g_count == 0 on entry to every kernel_launch call.
// (zero at static init; the last block restores them before exiting.)
__device__ float    g_v[ROWS];          // v[e,h] = sum_t mask[e,t]*hidden[t,h]
__device__ float    g_w[ROWS];          // w[e,h] = sum_f W[e,h,f] (always overwritten)
__device__ unsigned g_count;            // retirement counter

__global__ void __launch_bounds__(256)
fused_kernel(const float* __restrict__ hidden,
             const float* __restrict__ mask,
             const float* __restrict__ W,
             float* __restrict__ out, int out_size)
{
    const int tid = threadIdx.x;
    const int bid = blockIdx.x;

    __shared__ float  smask[NEXP][64];  // v-path mask chunk
    __shared__ double sred[256];        // last-block reduction
    __shared__ bool   s_last;

    if (bid < NV_BLOCKS) {
        // ------------------- v path: 16 MB hidden read --------------------
        const int chunk = bid >> 1;             // 0..31  (64-token chunk)
        const int cg    = bid & 1;              // 0..1   (column half)
        const int t0    = chunk * 64;

        for (int i = tid; i < NEXP * 64; i += 256) {
            int e = i >> 6, t = i & 63;
            smask[e][t] = mask[e * NTOK + t0 + t];
        }
        __syncthreads();

        const int h4 = cg * 256 + tid;          // float4 column index, 0..511
        float acc[NEXP][4];
        #pragma unroll
        for (int e = 0; e < NEXP; e++)
            #pragma unroll
            for (int c = 0; c < 4; c++) acc[e][c] = 0.0f;

        const float4* hid4 = reinterpret_cast<const float4*>(hidden);
        #pragma unroll 4
        for (int tt = 0; tt < 64; ++tt) {
            float4 hv = hid4[(size_t)(t0 + tt) * (HDIM / 4) + h4];
            #pragma unroll
            for (int e = 0; e < NEXP; e++) {
                float m = smask[e][tt];
                acc[e][0] = fmaf(m, hv.x, acc[e][0]);
                acc[e][1] = fmaf(m, hv.y, acc[e][1]);
                acc[e][2] = fmaf(m, hv.z, acc[e][2]);
                acc[e][3] = fmaf(m, hv.w, acc[e][3]);
            }
        }

        const int h = h4 * 4;
        #pragma unroll
        for (int e = 0; e < NEXP; e++)
            #pragma unroll
            for (int c = 0; c < 4; c++)
                atomicAdd(&g_v[e * HDIM + h + c], acc[e][c]);
    } else {
        // ------------------- W path: 256 MB streaming read ----------------
        const int wb   = bid - NV_BLOCKS;
        const int warp = tid >> 5;
        const int lane = tid & 31;
        const int row  = wb * ROWS_PER_BLOCK + warp;   // 0..16383

        const float4* w4 = reinterpret_cast<const float4*>(W + (size_t)row * FDIM);

        float s = 0.0f;
        #pragma unroll
        for (int i = 0; i < FDIM / 128; ++i) {         // 32 independent LDG.128
            float4 v = __ldcs(&w4[i * 32 + lane]);     // streaming: read-once
            s += (v.x + v.y) + (v.z + v.w);
        }
        #pragma unroll
        for (int off = 16; off; off >>= 1)
            s += __shfl_xor_sync(0xffffffffu, s, off);

        if (lane == 0) g_w[row] = s;
    }

    // ------------------- retirement + fused finalize -----------------------
    __threadfence();                 // release: make this block's writes visible
    __syncthreads();
    if (tid == 0) {
        unsigned t = atomicAdd(&g_count, 1u);
        s_last = (t == TOTAL_BLOCKS - 1);
    }
    __syncthreads();

    if (s_last) {
        __threadfence();             // acquire side

        double local = 0.0;
        for (int i = tid; i < ROWS; i += 256)
            local += (double)__ldcg(&g_w[i]) * (double)__ldcg(&g_v[i]);
        sred[tid] = local;
        __syncthreads();
        #pragma unroll
        for (int s2 = 128; s2; s2 >>= 1) {
            if (tid < s2) sred[tid] += sred[tid + s2];
            __syncthreads();
        }

        // Restore scratch invariants for the next graph replay.
        for (int i = tid; i < ROWS; i += 256) g_v[i] = 0.0f;
        if (tid == 0) g_count = 0u;

        // Emit the scalar (out poisoned to 0xAA; write every element).
        for (int i = tid; i < out_size; i += 256)
            out[i] = (i == 0) ? (float)sred[0] : 0.0f;
    }
}

// ---------------------------------------------------------------------------
// Launch contract
//   d_in[0] = hidden_4d   [1,1,T,H]   float32  (T*H elements)
//   d_in[1] = gate_up_proj[1,E,H,F]   float32  (E*H*F elements)
//   d_in[2] = sparsity    [1,E,T,1]   float32  (E*T elements)
//   d_out   = scalar float32
// ---------------------------------------------------------------------------
extern "C" void kernel_launch(void* const* d_in, const int* in_sizes, int n_in,
                              void* d_out, int out_size) {
    const float* hidden = (const float*)d_in[0];
    const float* W      = (const float*)d_in[1];
    const float* mask   = (const float*)d_in[2];
    float* out          = (float*)d_out;

    fused_kernel<<<TOTAL_BLOCKS, 256>>>(hidden, mask, W, out, out_size);
}